// round 17
// baseline (speedup 1.0000x reference)
#include <cuda_runtime.h>
#include <cstdint>

// Problem constants
constexpr int NN   = 100000;   // nodes
constexpr int EE   = 1600000;  // edges
constexpr int IND  = 256;
constexpr int HIDD = 128;
constexpr int OUTD = 32;

typedef unsigned long long ull;

constexpr int TB     = 256;
constexpr int G_DEG  = EE / TB;              // 6250 (exact)
constexpr int G_GEMM = (NN + 127) / 128;     // 782
constexpr int G_FILL = EE / TB;              // 6250 (exact)

// Scratch (static device arrays; no allocation allowed)
__device__ ull   g_pdeg[NN];       // packed: cnt<<40 | fixed-point(sum w, 2^20)
__device__ int   g_done;           // deg-block completion counter (self-reset)
__device__ int   g_scan_done;      // scan completion flag (reset by agg1)
__device__ int   g_cnt[NN];        // in-edge count per dst (no self-loop)
__device__ int   g_off[NN];        // CSR row offsets (exclusive prefix of cnt)
__device__ int   g_cur[NN];        // fill cursors
__device__ float g_inv[NN];        // deg^{-1/2}
__device__ int2  g_edge[EE];       // CSR: {src, __float_as_int(norm)} per slot
__device__ float g_h1[(size_t)NN * HIDD];   // x @ W1
__device__ float g_h2[(size_t)NN * OUTD];   // relu(x_emb) @ W2

// ---------------------------------------------------------------------------
// per-block edge dtype probe: true int64 edge_index values all lie in [0,NN);
// int32 read as int64 fuses two indices -> huge values. 16 probes, L2-hit.
// ---------------------------------------------------------------------------
__device__ __forceinline__ int block_probe_is32(const long long* __restrict__ ei,
                                                int* s_flag) {
    if (threadIdx.x == 0) {
        int ok = 1;
        for (int t = 0; t < 16; t++) {
            long long v = ei[t];
            if (v < 0 || v >= NN) { ok = 0; break; }
        }
        *s_flag = ok ? 0 : 1;
    }
    __syncthreads();
    return *s_flag;
}

__device__ __forceinline__ int load_idx(const long long* ei, size_t pos, int is32) {
    return is32 ? ((const int*)ei)[pos] : (int)ei[pos];
}

// tf32 round-to-nearest conversion (result stays in a 32-bit float container)
__device__ __forceinline__ float to_tf32(float f) {
    unsigned o;
    asm("cvt.rna.tf32.f32 %0, %1;" : "=r"(o) : "f"(f));
    return __uint_as_float(o);
}

// ---------------------------------------------------------------------------
// FUSED kernel 1 (three block ranges, bid-ordered):
//   [0, G_DEG)                : degree accumulation; LAST deg block runs the
//                               scan and sets g_scan_done.
//   [G_DEG, G_DEG+G_GEMM)     : tf32 GEMM1 h1 = x @ W1 (fragment-ordered smem)
//   [G_DEG+G_GEMM, ..+G_FILL) : CSR fill; spins (nanosleep) until g_scan_done,
//                               then scatters edges. Runs concurrent with the
//                               gemm tail. No deadlock: dispatch is bid-ordered
//                               and the flag setter (deg path) depends on
//                               nothing downstream.
// ---------------------------------------------------------------------------
__global__ __launch_bounds__(256, 2)
void k_fused1(const float* __restrict__ X, const float* __restrict__ W,
              const long long* __restrict__ ei, const float* __restrict__ ew) {
    __shared__ __align__(16) float sA[4096];   // A fragments: 4 kg x 8 mb x 128
    __shared__ __align__(16) float sB[4096];   // B fragments: 4 kg x 16 nb x 64
    __shared__ int s_misc[257];                // probe flag + scan sums

    int tid = threadIdx.x;

    if (blockIdx.x < G_DEG) {
        // ================= degree path =================
        int is32 = block_probe_is32(ei, &s_misc[256]);
        int e = blockIdx.x * TB + tid;         // e < EE (G_DEG * TB == EE)
        int d = load_idx(ei, (size_t)EE + e, is32);
        if ((unsigned)d < (unsigned)NN) {
            unsigned wq = __float2uint_rn(ew[e] * 1048576.0f);   // 2^20 fixed pt
            atomicAdd(&g_pdeg[d], ((ull)1 << 40) | (ull)wq);
        }
        __threadfence();
        __syncthreads();
        if (tid == 0)
            s_misc[256] = (atomicAdd(&g_done, 1) == G_DEG - 1) ? 1 : 0;
        __syncthreads();
        if (!s_misc[256]) return;

        // ---- last deg block: scan (concurrent with gemm blocks) ----
        __threadfence();
        for (int i = tid; i < NN; i += TB) {
            ull p = g_pdeg[i];
            g_pdeg[i] = 0;
            int c = (int)(p >> 40);
            float dg = 1.0f + (float)(p & 0xFFFFFFFFFFull) * (1.0f / 1048576.0f);
            g_inv[i] = rsqrtf(dg);
            g_cnt[i] = c;
        }
        __syncthreads();
        const int CH = (NN + TB - 1) / TB;       // 391
        int lo = tid * CH;
        int hi = lo + CH < NN ? lo + CH : NN;
        int s = 0;
        for (int i = lo; i < hi; i++) s += g_cnt[i];
        s_misc[tid] = s;
        __syncthreads();
        if (tid == 0) {
            int run = 0;
            for (int i = 0; i < TB; i++) { int v = s_misc[i]; s_misc[i] = run; run += v; }
            g_done = 0;                           // reset for next replay
        }
        __syncthreads();
        int run = s_misc[tid];
        for (int i = lo; i < hi; i++) {
            g_off[i] = run;
            g_cur[i] = run;
            run += g_cnt[i];
        }
        __syncthreads();
        if (tid == 0) {
            __threadfence();
            atomicExch(&g_scan_done, 1);          // release fill blocks
        }
        return;
    }

    if (blockIdx.x >= G_DEG + G_GEMM) {
        // ================= fill path =================
        if (tid == 0) {
            while (atomicAdd(&g_scan_done, 0) == 0) __nanosleep(200);
        }
        __syncthreads();
        __threadfence();
        int is32 = block_probe_is32(ei, &s_misc[256]);
        int e = (blockIdx.x - G_DEG - G_GEMM) * TB + tid;   // < EE exact
        int s = load_idx(ei, (size_t)e, is32);
        int d = load_idx(ei, (size_t)EE + e, is32);
        if ((unsigned)s < (unsigned)NN && (unsigned)d < (unsigned)NN) {
            int pos = atomicAdd(&g_cur[d], 1);
            float nw = g_inv[s] * ew[e] * g_inv[d];
            g_edge[pos] = make_int2(s, __float_as_int(nw));
        }
        return;
    }

    // ================= gemm path: h1 = x @ W1 (tf32) =================
    constexpr int KK = IND;                   // 256
    int lane = tid & 31, wid = tid >> 5;
    int wm   = wid & 3,  wn  = wid >> 2;      // warp grid 4 (M) x 2 (N)
    int g    = lane >> 2, c  = lane & 3;
    int row0 = (blockIdx.x - G_DEG) * 128;

    float d[2][8][4];
#pragma unroll
    for (int mt = 0; mt < 2; mt++)
#pragma unroll
        for (int nt = 0; nt < 8; nt++)
#pragma unroll
            for (int r = 0; r < 4; r++) d[mt][nt][r] = 0.0f;

    for (int k0 = 0; k0 < KK; k0 += 32) {
        // A g2s, fragment-ordered
#pragma unroll
        for (int l = 0; l < 4; l++) {
            int idx = tid + l * 256;
            int r   = idx >> 3;
            int kc  = (idx & 7) << 2;
            int gr  = row0 + r;
            float4 v = make_float4(0.f, 0.f, 0.f, 0.f);
            if (gr < NN) v = *(const float4*)(X + (size_t)gr * KK + k0 + kc);
            float vv[4] = {v.x, v.y, v.z, v.w};
            int mb = r >> 4;
            int mhalf = (r & 15) >= 8 ? 1 : 0;
            int lbase = (r & 7) << 2;
#pragma unroll
            for (int j = 0; j < 4; j++) {
                int kl = kc + j;
                int kg = kl >> 3;
                int rr = (((kl & 7) >= 4) ? 2 : 0) + mhalf;
                sA[(((kg << 3) + mb) << 7) + ((lbase + (kl & 3)) << 2) + rr] =
                    to_tf32(vv[j]);
            }
        }
        // B g2s, fragment-ordered
#pragma unroll
        for (int l = 0; l < 4; l++) {
            int idx = tid + l * 256;
            int kk  = idx >> 5;
            int cc  = (idx & 31) << 2;
            float4 v = *(const float4*)(W + (size_t)(k0 + kk) * HIDD + cc);
            float vv[4] = {v.x, v.y, v.z, v.w};
            int kg = kk >> 3;
            int rr = ((kk & 7) >= 4) ? 1 : 0;
            int cl = kk & 3;
#pragma unroll
            for (int j = 0; j < 4; j++) {
                int nl = cc + j;
                sB[(((kg << 4) + (nl >> 3)) << 6) + ((((nl & 7) << 2) + cl) << 1) + rr] =
                    to_tf32(vv[j]);
            }
        }
        __syncthreads();

#pragma unroll
        for (int kg = 0; kg < 4; kg++) {
            unsigned a[2][4];
#pragma unroll
            for (int mt = 0; mt < 2; mt++) {
                float4 av = *(const float4*)(&sA[(((kg << 3) + wm * 2 + mt) << 7) + (lane << 2)]);
                a[mt][0] = __float_as_uint(av.x);
                a[mt][1] = __float_as_uint(av.y);
                a[mt][2] = __float_as_uint(av.z);
                a[mt][3] = __float_as_uint(av.w);
            }
            unsigned b[8][2];
#pragma unroll
            for (int nt = 0; nt < 8; nt++) {
                float2 bv = *(const float2*)(&sB[(((kg << 4) + wn * 8 + nt) << 6) + (lane << 1)]);
                b[nt][0] = __float_as_uint(bv.x);
                b[nt][1] = __float_as_uint(bv.y);
            }
#pragma unroll
            for (int mt = 0; mt < 2; mt++)
#pragma unroll
                for (int nt = 0; nt < 8; nt++) {
                    asm volatile(
                        "mma.sync.aligned.m16n8k8.row.col.f32.tf32.tf32.f32 "
                        "{%0,%1,%2,%3}, {%4,%5,%6,%7}, {%8,%9}, {%0,%1,%2,%3};"
                        : "+f"(d[mt][nt][0]), "+f"(d[mt][nt][1]),
                          "+f"(d[mt][nt][2]), "+f"(d[mt][nt][3])
                        : "r"(a[mt][0]), "r"(a[mt][1]), "r"(a[mt][2]), "r"(a[mt][3]),
                          "r"(b[nt][0]), "r"(b[nt][1]));
                }
        }
        __syncthreads();
    }

#pragma unroll
    for (int mt = 0; mt < 2; mt++) {
        int r0 = row0 + wm * 32 + mt * 16 + g;
        int r1 = r0 + 8;
#pragma unroll
        for (int nt = 0; nt < 8; nt++) {
            int col = wn * 64 + nt * 8 + 2 * c;
            if (r0 < NN) {
                float2 v0 = make_float2(d[mt][nt][0], d[mt][nt][1]);
                *(float2*)(g_h1 + (size_t)r0 * HIDD + col) = v0;
            }
            if (r1 < NN) {
                float2 v1 = make_float2(d[mt][nt][2], d[mt][nt][3]);
                *(float2*)(g_h1 + (size_t)r1 * HIDD + col) = v1;
            }
        }
    }
}

// ---------------------------------------------------------------------------
// GEMM2 via tf32 tensor cores: g_h2[M,32] = relu(xemb)[M,128] @ W2[128,32]
// Same fragment-ordered scheme; warp tile 32x16 (2x2 m16n8k8 frags).
// ---------------------------------------------------------------------------
__global__ __launch_bounds__(256)
void k_gemm2_tf32(const float* __restrict__ X, const float* __restrict__ W) {
    constexpr int KK = HIDD;                  // 128
    __shared__ __align__(16) float sA[4096];  // 4 kg x 8 mb x 128
    __shared__ __align__(16) float sB[1024];  // 4 kg x 4 nb x 64

    int tid  = threadIdx.x;
    int lane = tid & 31, wid = tid >> 5;
    int wm   = wid & 3,  wn  = wid >> 2;      // warp grid 4 (M) x 2 (N)
    int g    = lane >> 2, c  = lane & 3;
    int row0 = blockIdx.x * 128;

    float d[2][2][4];
#pragma unroll
    for (int mt = 0; mt < 2; mt++)
#pragma unroll
        for (int nt = 0; nt < 2; nt++)
#pragma unroll
            for (int r = 0; r < 4; r++) d[mt][nt][r] = 0.0f;

    for (int k0 = 0; k0 < KK; k0 += 32) {
        // A g2s (relu folded), fragment-ordered
#pragma unroll
        for (int l = 0; l < 4; l++) {
            int idx = tid + l * 256;
            int r   = idx >> 3;
            int kc  = (idx & 7) << 2;
            int gr  = row0 + r;
            float4 v = make_float4(0.f, 0.f, 0.f, 0.f);
            if (gr < NN) v = *(const float4*)(X + (size_t)gr * KK + k0 + kc);
            v.x = fmaxf(v.x, 0.f); v.y = fmaxf(v.y, 0.f);
            v.z = fmaxf(v.z, 0.f); v.w = fmaxf(v.w, 0.f);
            float vv[4] = {v.x, v.y, v.z, v.w};
            int mb = r >> 4;
            int mhalf = (r & 15) >= 8 ? 1 : 0;
            int lbase = (r & 7) << 2;
#pragma unroll
            for (int j = 0; j < 4; j++) {
                int kl = kc + j;
                int kg = kl >> 3;
                int rr = (((kl & 7) >= 4) ? 2 : 0) + mhalf;
                sA[(((kg << 3) + mb) << 7) + ((lbase + (kl & 3)) << 2) + rr] =
                    to_tf32(vv[j]);
            }
        }
        // B g2s: 32x32 tile = 256 float4, 1 per thread
        {
            int idx = tid;
            int kk  = idx >> 3;                 // OUTD/4 = 8 float4 per row
            int cc  = (idx & 7) << 2;
            float4 v = *(const float4*)(W + (size_t)(k0 + kk) * OUTD + cc);
            float vv[4] = {v.x, v.y, v.z, v.w};
            int kg = kk >> 3;
            int rr = ((kk & 7) >= 4) ? 1 : 0;
            int cl = kk & 3;
#pragma unroll
            for (int j = 0; j < 4; j++) {
                int nl = cc + j;
                sB[(((kg << 2) + (nl >> 3)) << 6) + ((((nl & 7) << 2) + cl) << 1) + rr] =
                    to_tf32(vv[j]);
            }
        }
        __syncthreads();

#pragma unroll
        for (int kg = 0; kg < 4; kg++) {
            unsigned a[2][4];
#pragma unroll
            for (int mt = 0; mt < 2; mt++) {
                float4 av = *(const float4*)(&sA[(((kg << 3) + wm * 2 + mt) << 7) + (lane << 2)]);
                a[mt][0] = __float_as_uint(av.x);
                a[mt][1] = __float_as_uint(av.y);
                a[mt][2] = __float_as_uint(av.z);
                a[mt][3] = __float_as_uint(av.w);
            }
            unsigned b[2][2];
#pragma unroll
            for (int nt = 0; nt < 2; nt++) {
                int nb = wn * 2 + nt;
                float2 bv = *(const float2*)(&sB[(((kg << 2) + nb) << 6) + (lane << 1)]);
                b[nt][0] = __float_as_uint(bv.x);
                b[nt][1] = __float_as_uint(bv.y);
            }
#pragma unroll
            for (int mt = 0; mt < 2; mt++)
#pragma unroll
                for (int nt = 0; nt < 2; nt++) {
                    asm volatile(
                        "mma.sync.aligned.m16n8k8.row.col.f32.tf32.tf32.f32 "
                        "{%0,%1,%2,%3}, {%4,%5,%6,%7}, {%8,%9}, {%0,%1,%2,%3};"
                        : "+f"(d[mt][nt][0]), "+f"(d[mt][nt][1]),
                          "+f"(d[mt][nt][2]), "+f"(d[mt][nt][3])
                        : "r"(a[mt][0]), "r"(a[mt][1]), "r"(a[mt][2]), "r"(a[mt][3]),
                          "r"(b[nt][0]), "r"(b[nt][1]));
                }
        }
        __syncthreads();
    }

#pragma unroll
    for (int mt = 0; mt < 2; mt++) {
        int r0 = row0 + wm * 32 + mt * 16 + g;
        int r1 = r0 + 8;
#pragma unroll
        for (int nt = 0; nt < 2; nt++) {
            int col = wn * 16 + nt * 8 + 2 * c;
            if (r0 < NN) {
                float2 v0 = make_float2(d[mt][nt][0], d[mt][nt][1]);
                *(float2*)(g_h2 + (size_t)r0 * OUTD + col) = v0;
            }
            if (r1 < NN) {
                float2 v1 = make_float2(d[mt][nt][2], d[mt][nt][3]);
                *(float2*)(g_h2 + (size_t)r1 * OUTD + col) = v1;
            }
        }
    }
}

// ---------------------------------------------------------------------------
// CSR aggregation, layer 1 (unroll-4): one warp per node, lane owns float4.
// out = sum_{e in in(n)} norm_e * h1[src_e] + inv(n)^2 * h1[n] + b1
// Block 0 also resets g_scan_done for the next replay.
// ---------------------------------------------------------------------------
__global__ void k_agg1(float* __restrict__ xemb, const float* __restrict__ b1) {
    if (blockIdx.x == 0 && threadIdx.x == 0) g_scan_done = 0;

    int warp = (blockIdx.x * blockDim.x + threadIdx.x) >> 5;
    int lane = threadIdx.x & 31;
    if (warp >= NN) return;

    int beg = g_off[warp];
    int cnt = g_cnt[warp];
    float iv = g_inv[warp];
    float inv2 = iv * iv;

    size_t off = (size_t)warp * HIDD + lane * 4;
    float4 h = *(const float4*)(g_h1 + off);
    float4 b = *(const float4*)(b1 + lane * 4);
    float4 acc;
    acc.x = inv2 * h.x + b.x;
    acc.y = inv2 * h.y + b.y;
    acc.z = inv2 * h.z + b.z;
    acc.w = inv2 * h.w + b.w;

    int i = 0;
    for (; i + 4 <= cnt; i += 4) {
        int2 p0 = g_edge[beg + i + 0], p1 = g_edge[beg + i + 1];
        int2 p2 = g_edge[beg + i + 2], p3 = g_edge[beg + i + 3];
        float n0 = __int_as_float(p0.y), n1 = __int_as_float(p1.y);
        float n2 = __int_as_float(p2.y), n3 = __int_as_float(p3.y);
        float4 v0 = *(const float4*)(g_h1 + (size_t)p0.x * HIDD + lane * 4);
        float4 v1 = *(const float4*)(g_h1 + (size_t)p1.x * HIDD + lane * 4);
        float4 v2 = *(const float4*)(g_h1 + (size_t)p2.x * HIDD + lane * 4);
        float4 v3 = *(const float4*)(g_h1 + (size_t)p3.x * HIDD + lane * 4);
        acc.x += n0 * v0.x + n1 * v1.x + n2 * v2.x + n3 * v3.x;
        acc.y += n0 * v0.y + n1 * v1.y + n2 * v2.y + n3 * v3.y;
        acc.z += n0 * v0.z + n1 * v1.z + n2 * v2.z + n3 * v3.z;
        acc.w += n0 * v0.w + n1 * v1.w + n2 * v2.w + n3 * v3.w;
    }
    for (; i < cnt; i++) {
        int2 p = g_edge[beg + i];
        float nw = __int_as_float(p.y);
        float4 v = *(const float4*)(g_h1 + (size_t)p.x * HIDD + lane * 4);
        acc.x += nw * v.x; acc.y += nw * v.y;
        acc.z += nw * v.z; acc.w += nw * v.w;
    }
    *(float4*)(xemb + off) = acc;
}

// layer 2: 32 features -> one float per lane (unroll-4)
__global__ void k_agg2(float* __restrict__ outp, const float* __restrict__ b2) {
    int warp = (blockIdx.x * blockDim.x + threadIdx.x) >> 5;
    int lane = threadIdx.x & 31;
    if (warp >= NN) return;

    int beg = g_off[warp];
    int cnt = g_cnt[warp];
    float iv = g_inv[warp];
    float inv2 = iv * iv;

    size_t off = (size_t)warp * OUTD + lane;
    float acc = inv2 * g_h2[off] + b2[lane];

    int i = 0;
    for (; i + 4 <= cnt; i += 4) {
        int2 p0 = g_edge[beg + i + 0], p1 = g_edge[beg + i + 1];
        int2 p2 = g_edge[beg + i + 2], p3 = g_edge[beg + i + 3];
        acc += __int_as_float(p0.y) * g_h2[(size_t)p0.x * OUTD + lane]
             + __int_as_float(p1.y) * g_h2[(size_t)p1.x * OUTD + lane]
             + __int_as_float(p2.y) * g_h2[(size_t)p2.x * OUTD + lane]
             + __int_as_float(p3.y) * g_h2[(size_t)p3.x * OUTD + lane];
    }
    for (; i < cnt; i++) {
        int2 p = g_edge[beg + i];
        acc += __int_as_float(p.y) * g_h2[(size_t)p.x * OUTD + lane];
    }
    outp[off] = acc;
}

// ---------------------------------------------------------------------------
extern "C" void kernel_launch(void* const* d_in, const int* in_sizes, int n_in,
                              void* d_out, int out_size) {
    const float*     x  = (const float*)d_in[0];
    const long long* ei = (const long long*)d_in[1];   // int32 or int64 — probed
    const float*     ew = (const float*)d_in[2];
    const float*     W1 = (const float*)d_in[3];
    const float*     b1 = (const float*)d_in[4];
    const float*     W2 = (const float*)d_in[5];
    const float*     b2 = (const float*)d_in[6];

    float* outp = (float*)d_out;                       // [NN, OUTD]
    float* xemb = outp + (size_t)NN * OUTD;            // [NN, HIDD]

    // fused: degree -> scan (last deg block) || tf32 gemm1 || fill (spin on scan)
    k_fused1<<<G_DEG + G_GEMM + G_FILL, TB>>>(x, W1, ei, ew);
    // layer 1 aggregate (+self-loop +bias) -> xemb ; resets scan flag
    k_agg1<<<(NN * 32 + TB - 1) / TB, TB>>>(xemb, b1);
    // layer 2: h2 = relu(xemb) @ W2 (tf32) ; aggregate -> out
    k_gemm2_tf32<<<(NN + 127) / 128, TB>>>(xemb, W2);
    k_agg2<<<(NN * 32 + TB - 1) / TB, TB>>>(outp, b2);
}